// round 12
// baseline (speedup 1.0000x reference)
#include <cuda_runtime.h>
#include <cuda_fp16.h>
#include <cstddef>
#include <cstdint>

#define BDIM 128
#define LDIM 512
#define EHD  256
#define DHD  256
#define YD   8
#define NS   4          // L-chunks for flash context
#define LCH  (LDIM/NS)  // 128

// ---------------- device scratch (static, allocation-free) ----------------
__device__ __half g_projh[(size_t)BDIM * LDIM * EHD]; // 32MB fp16 proj
__device__ __half g_xh[(size_t)BDIM * LDIM * EHD];    // 32MB fp16 x
__device__ __half g_wh[EHD * EHD];                    // W1x fp16 [n][k]
__device__ float g_u[BDIM * EHD];
__device__ float g_h[2][BDIM * DHD];
__device__ float g_c[2][BDIM * DHD];
__device__ float g_yp[2][BDIM * YD];
__device__ float g_ctx[BDIM * EHD];
__device__ float g_pctx[BDIM * NS * EHD];
__device__ float g_ms[BDIM * NS * 2];   // (max, sum) per chunk

// grid-barrier state (monotonic generation; survives graph replays safely)
__device__ unsigned g_cnt = 0;
__device__ unsigned g_gen = 0;

// ---------------- math helpers ----------------
__device__ __forceinline__ float tanh_hw(float x) {
    float y; asm("tanh.approx.f32 %0, %1;" : "=f"(y) : "f"(x)); return y;
}
__device__ __forceinline__ float fast_tanh(float x) { // accurate, for LSTM
    float e = __expf(2.0f * x);
    return 1.0f - __fdividef(2.0f, e + 1.0f);
}
__device__ __forceinline__ float fast_sig(float x) {
    return __fdividef(1.0f, 1.0f + __expf(-x));
}
__device__ __forceinline__ float warp_sum(float v) {
    #pragma unroll
    for (int o = 16; o > 0; o >>= 1) v += __shfl_xor_sync(0xffffffffu, v, o);
    return v;
}
__device__ __forceinline__ float warp_max(float v) {
    #pragma unroll
    for (int o = 16; o > 0; o >>= 1) v = fmaxf(v, __shfl_xor_sync(0xffffffffu, v, o));
    return v;
}
__device__ __forceinline__ void mma_f16(float c[4], const uint32_t a[4],
                                        const uint32_t b[2]) {
    asm volatile(
        "mma.sync.aligned.m16n8k16.row.col.f32.f16.f16.f32 "
        "{%0,%1,%2,%3}, {%4,%5,%6,%7}, {%8,%9}, {%0,%1,%2,%3};\n"
        : "+f"(c[0]), "+f"(c[1]), "+f"(c[2]), "+f"(c[3])
        : "r"(a[0]), "r"(a[1]), "r"(a[2]), "r"(a[3]), "r"(b[0]), "r"(b[1]));
}

// grid sync: counter + generation. All NB blocks are co-resident (grid sized
// from occupancy), so spinning is deadlock-free. my_gen lives in thread 0.
__device__ __forceinline__ void gsync(unsigned nb, unsigned& my_gen) {
    __syncthreads();
    if (threadIdx.x == 0) {
        my_gen++;
        __threadfence();
        unsigned t = atomicAdd(&g_cnt, 1);
        if (t == nb - 1) {
            g_cnt = 0;
            __threadfence();
            atomicExch(&g_gen, my_gen);
        } else {
            while ((int)(*(volatile unsigned*)&g_gen - my_gen) < 0) __nanosleep(64);
        }
        __threadfence();
    }
    __syncthreads();
}

// ---------------- init + converts ----------------
__global__ void k_init(const float* __restrict__ yh) {
    int i = blockIdx.x * blockDim.x + threadIdx.x;
    if (i < BDIM * DHD) { g_h[0][i] = 0.0f; g_c[0][i] = 0.0f; }
    if (i < BDIM * YD)  { g_yp[0][i] = yh[i]; }
}

__global__ __launch_bounds__(256) void k_convx(const float* __restrict__ x) {
    const int n4 = (BDIM * LDIM * EHD) / 4;
    for (int i = blockIdx.x * blockDim.x + threadIdx.x; i < n4;
         i += gridDim.x * blockDim.x) {
        float4 v = *(const float4*)(x + (size_t)i * 4);
        __half2 p0 = __floats2half2_rn(v.x, v.y);
        __half2 p1 = __floats2half2_rn(v.z, v.w);
        uint2 o; o.x = *(uint32_t*)&p0; o.y = *(uint32_t*)&p1;
        *(uint2*)(g_xh + (size_t)i * 4) = o;
    }
}

__global__ __launch_bounds__(256) void k_convw(const float* __restrict__ W1) {
    int i = blockIdx.x * blockDim.x + threadIdx.x;
    int row = i >> 6;
    int c4 = (i & 63) * 4;
    float4 v = *(const float4*)(W1 + (size_t)row * 768 + 512 + c4);
    __half2 p0 = __floats2half2_rn(v.x, v.y);
    __half2 p1 = __floats2half2_rn(v.z, v.w);
    uint2 o; o.x = *(uint32_t*)&p0; o.y = *(uint32_t*)&p1;
    *(uint2*)(g_wh + (size_t)row * 256 + c4) = o;
}

// ---------------- tensor-core proj GEMM (unchanged, validated) ---------------
__global__ __launch_bounds__(256) void k_projmma() {
    __shared__ __half As[128][72];
    __shared__ __half Bs[128][72];
    const int bm = blockIdx.y * 128;
    const int bn = blockIdx.x * 128;
    const int tid = threadIdx.x;
    const int wid = tid >> 5, ln = tid & 31;
    const int wm = wid & 3, wn = wid >> 2;
    const int g = ln >> 2, tg2 = (ln & 3) * 2;

    float acc[2][8][4];
    #pragma unroll
    for (int mi = 0; mi < 2; mi++)
        #pragma unroll
        for (int ni = 0; ni < 8; ni++)
            #pragma unroll
            for (int q = 0; q < 4; q++) acc[mi][ni][q] = 0.0f;

    for (int kc = 0; kc < 4; kc++) {
        const int kb = kc * 64;
        #pragma unroll
        for (int it = 0; it < 4; it++) {
            int idx = it * 256 + tid;
            int row = idx >> 3;
            int col8 = (idx & 7) * 8;
            uint4 av = *(const uint4*)(g_xh + (size_t)(bm + row) * 256 + kb + col8);
            uint4 bv = *(const uint4*)(g_wh + (size_t)(bn + row) * 256 + kb + col8);
            *(uint4*)&As[row][col8] = av;
            *(uint4*)&Bs[row][col8] = bv;
        }
        __syncthreads();

        #pragma unroll
        for (int ks = 0; ks < 64; ks += 16) {
            uint32_t a[2][4], bf[8][2];
            #pragma unroll
            for (int mi = 0; mi < 2; mi++) {
                int mb = wm * 32 + mi * 16;
                a[mi][0] = *(const uint32_t*)&As[mb + g][ks + tg2];
                a[mi][1] = *(const uint32_t*)&As[mb + g + 8][ks + tg2];
                a[mi][2] = *(const uint32_t*)&As[mb + g][ks + tg2 + 8];
                a[mi][3] = *(const uint32_t*)&As[mb + g + 8][ks + tg2 + 8];
            }
            #pragma unroll
            for (int ni = 0; ni < 8; ni++) {
                int nb = wn * 64 + ni * 8;
                bf[ni][0] = *(const uint32_t*)&Bs[nb + g][ks + tg2];
                bf[ni][1] = *(const uint32_t*)&Bs[nb + g][ks + tg2 + 8];
            }
            #pragma unroll
            for (int mi = 0; mi < 2; mi++)
                #pragma unroll
                for (int ni = 0; ni < 8; ni++)
                    mma_f16(acc[mi][ni], a[mi], bf[ni]);
        }
        __syncthreads();
    }

    #pragma unroll
    for (int mi = 0; mi < 2; mi++) {
        int r0 = bm + wm * 32 + mi * 16 + g;
        #pragma unroll
        for (int ni = 0; ni < 8; ni++) {
            int col = bn + wn * 64 + ni * 8 + tg2;
            __half2 p0 = __floats2half2_rn(acc[mi][ni][0], acc[mi][ni][1]);
            __half2 p1 = __floats2half2_rn(acc[mi][ni][2], acc[mi][ni][3]);
            *(uint32_t*)&g_projh[(size_t)r0 * 256 + col] = *(uint32_t*)&p0;
            *(uint32_t*)&g_projh[(size_t)(r0 + 8) * 256 + col] = *(uint32_t*)&p1;
        }
    }
}

// ---------------- persistent step kernel -------------------------------------
// Runs all T steps. Per step: phase A (u + y_pred(t-1)), phase B (flash ctx),
// phase C (combine + y_tilde + LSTM), separated by grid barriers.
// Step-varying cross-block data is read with __ldcg (L1 not coherent);
// read-only arrays (proj/x/weights) stay L1-cacheable across steps.
struct SmA { float Ws[16][513]; };
struct SmB { float u_s[EHD]; float w2_s[EHD]; float sc[LCH]; float red[8]; float part[2][EHD]; };
struct SmC { float Ws[32][257]; float Wi_s[32][9]; float bias_s[32];
             float gv[4][64]; float ctx_s[8][EHD]; float yt_s[8][YD]; };
union SmU { SmA a; SmB b; SmC c; };

__global__ __launch_bounds__(256) void k_persist(
    const float* __restrict__ W1,  const float* __restrict__ b1,
    const float* __restrict__ w2,
    const float* __restrict__ Whh, const float* __restrict__ Wih,
    const float* __restrict__ bih, const float* __restrict__ bhh,
    const float* __restrict__ Wfc, const float* __restrict__ bfc,
    const float* __restrict__ Wfin, const float* __restrict__ bfin,
    float* __restrict__ out, int T, int NB)
{
    __shared__ SmU sm;
    const int tid = threadIdx.x;
    const int bid = blockIdx.x;
    unsigned my_gen = 0;
    if (tid == 0) my_gen = *(volatile unsigned*)&g_gen;

    for (int t = 0; ; t++) {
        const int cur = t & 1, nxt = cur ^ 1;

        // ================= phase A: u(t) + y_pred(t-1) =================
        for (int ch = bid; ch < 144; ch += NB) {
            if (ch < 128) {
                if (t < T) {
                    const int j0 = (ch & 15) * 16;
                    const int b0 = (ch >> 4) * 16;
                    for (int idx = tid; idx < 16 * 128; idx += 256) {
                        int row = idx >> 7;
                        int col = (idx & 127) << 2;
                        float4 v = *(const float4*)(W1 + (size_t)(j0 + row) * 768 + col);
                        sm.a.Ws[row][col + 0] = v.x; sm.a.Ws[row][col + 1] = v.y;
                        sm.a.Ws[row][col + 2] = v.z; sm.a.Ws[row][col + 3] = v.w;
                    }
                    __syncthreads();
                    const int jl = tid & 15, bl = tid >> 4;
                    const int j = j0 + jl, b = b0 + bl;
                    const float4* h4 = (const float4*)(g_h[cur] + b * DHD);
                    const float4* c4 = (const float4*)(g_c[cur] + b * DHD);
                    float s = b1[j];
                    #pragma unroll 8
                    for (int k4 = 0; k4 < 64; k4++) {
                        float4 hv = __ldcg(h4 + k4);
                        float4 cv = __ldcg(c4 + k4);
                        int k = k4 << 2;
                        s += sm.a.Ws[jl][k] * hv.x + sm.a.Ws[jl][k + 1] * hv.y
                           + sm.a.Ws[jl][k + 2] * hv.z + sm.a.Ws[jl][k + 3] * hv.w;
                        s += sm.a.Ws[jl][256 + k] * cv.x + sm.a.Ws[jl][257 + k] * cv.y
                           + sm.a.Ws[jl][258 + k] * cv.z + sm.a.Ws[jl][259 + k] * cv.w;
                    }
                    g_u[b * EHD + j] = s;
                    __syncthreads();
                }
            } else {
                if (t > 0) {
                    const int w = tid >> 5, ln = tid & 31;
                    const int b = (ch - 128) * 8 + w;
                    const float* h  = g_h[cur] + b * DHD;
                    const float* cx = g_ctx + b * EHD;
                    #pragma unroll
                    for (int y = 0; y < YD; y++) {
                        const float* wr = Wfin + y * 512;
                        float s = 0.0f;
                        #pragma unroll
                        for (int k = ln; k < 256; k += 32)
                            s += wr[k] * __ldcg(h + k) + wr[256 + k] * __ldcg(cx + k);
                        s = warp_sum(s);
                        if (ln == 0) {
                            float v = s + bfin[y];
                            out[((size_t)b * T + (t - 1)) * YD + y] = v;
                            g_yp[cur][b * YD + y] = v;
                        }
                    }
                }
            }
        }
        if (t == T) break;
        gsync((unsigned)NB, my_gen);

        // ================= phase B: flash scores + partial context =====
        for (int ch = bid; ch < BDIM * NS; ch += NB) {
            const int b = ch >> 2;
            const int c = ch & 3;
            const int l0 = c * LCH;
            const int w = tid >> 5, ln = tid & 31;

            sm.b.u_s[tid]  = __ldcg(&g_u[b * EHD + tid]);
            sm.b.w2_s[tid] = w2[tid];
            __syncthreads();

            const int j0 = ln << 3;
            const float uw0 = sm.b.u_s[j0],     uw1 = sm.b.u_s[j0 + 1];
            const float uw2 = sm.b.u_s[j0 + 2], uw3 = sm.b.u_s[j0 + 3];
            const float uw4 = sm.b.u_s[j0 + 4], uw5 = sm.b.u_s[j0 + 5];
            const float uw6 = sm.b.u_s[j0 + 6], uw7 = sm.b.u_s[j0 + 7];
            const float w20 = sm.b.w2_s[j0],     w21 = sm.b.w2_s[j0 + 1];
            const float w22 = sm.b.w2_s[j0 + 2], w23 = sm.b.w2_s[j0 + 3];
            const float w24 = sm.b.w2_s[j0 + 4], w25 = sm.b.w2_s[j0 + 5];
            const float w26 = sm.b.w2_s[j0 + 6], w27 = sm.b.w2_s[j0 + 7];
            for (int li = 0; li < 16; li++) {
                int l = w * 16 + li;
                const uint4* p = (const uint4*)(g_projh + ((size_t)(b * LDIM + l0 + l)) * EHD);
                uint4 pv = p[ln];
                float2 f0 = __half22float2(*(__half2*)&pv.x);
                float2 f1 = __half22float2(*(__half2*)&pv.y);
                float2 f2 = __half22float2(*(__half2*)&pv.z);
                float2 f3 = __half22float2(*(__half2*)&pv.w);
                float s = w20 * tanh_hw(f0.x + uw0) + w21 * tanh_hw(f0.y + uw1)
                        + w22 * tanh_hw(f1.x + uw2) + w23 * tanh_hw(f1.y + uw3)
                        + w24 * tanh_hw(f2.x + uw4) + w25 * tanh_hw(f2.y + uw5)
                        + w26 * tanh_hw(f3.x + uw6) + w27 * tanh_hw(f3.y + uw7);
                s = warp_sum(s);
                if (ln == 0) sm.b.sc[l] = s;
            }
            __syncthreads();

            float v = (tid < LCH) ? sm.b.sc[tid] : -1e30f;
            float m = warp_max(v);
            if (ln == 0) sm.b.red[w] = m;
            __syncthreads();
            float mx = sm.b.red[0];
            #pragma unroll
            for (int i = 1; i < 8; i++) mx = fmaxf(mx, sm.b.red[i]);
            __syncthreads();

            float e = 0.0f;
            if (tid < LCH) { e = __expf(sm.b.sc[tid] - mx); sm.b.sc[tid] = e; }
            float ssum = warp_sum(e);
            if (ln == 0) sm.b.red[w] = ssum;
            __syncthreads();
            float stot = sm.b.red[0] + sm.b.red[1] + sm.b.red[2] + sm.b.red[3]
                       + sm.b.red[4] + sm.b.red[5] + sm.b.red[6] + sm.b.red[7];

            const int half = tid >> 7;
            const int jp = (tid & 127) * 2;
            const __half* xb = g_xh + ((size_t)(b * LDIM + l0 + half * 64)) * EHD + jp;
            float a0 = 0.0f, a1 = 0.0f;
            #pragma unroll 4
            for (int l = 0; l < 64; l++) {
                uint32_t pv = *(const uint32_t*)(xb + (size_t)l * EHD);
                float2 f = __half22float2(*(__half2*)&pv);
                float wv = sm.b.sc[half * 64 + l];
                a0 += wv * f.x; a1 += wv * f.y;
            }
            sm.b.part[half][jp] = a0; sm.b.part[half][jp + 1] = a1;
            __syncthreads();

            g_pctx[(b * NS + c) * EHD + tid] = sm.b.part[0][tid] + sm.b.part[1][tid];
            if (tid == 0) {
                g_ms[(b * NS + c) * 2 + 0] = mx;
                g_ms[(b * NS + c) * 2 + 1] = stot;
            }
            __syncthreads();
        }
        gsync((unsigned)NB, my_gen);

        // ================= phase C: combine + y_tilde + LSTM ===========
        for (int ch = bid; ch < 512; ch += NB) {
            const int j0 = (ch & 31) * 8;
            const int b0 = (ch >> 5) * 8;

            for (int idx = tid; idx < 32 * 64; idx += 256) {
                int row = idx >> 6;
                int col = (idx & 63) << 2;
                int g = (row >> 3) * 256 + j0 + (row & 7);
                float4 v = *(const float4*)(Whh + (size_t)g * 256 + col);
                sm.c.Ws[row][col + 0] = v.x; sm.c.Ws[row][col + 1] = v.y;
                sm.c.Ws[row][col + 2] = v.z; sm.c.Ws[row][col + 3] = v.w;
            }
            {
                int row = tid >> 3, k = tid & 7;
                int g = (row >> 3) * 256 + j0 + (row & 7);
                sm.c.Wi_s[row][k] = Wih[(size_t)g * 8 + k];
                if (tid < 32) {
                    int gg = (tid >> 3) * 256 + j0 + (tid & 7);
                    sm.c.bias_s[tid] = bih[gg] + bhh[gg];
                }
            }

            {   // combine partial contexts (warp bb -> batch b0+bb)
                const int bb = tid >> 5, ln = tid & 31;
                const int b = b0 + bb;
                float m0 = __ldcg(&g_ms[(b * NS + 0) * 2]), s0 = __ldcg(&g_ms[(b * NS + 0) * 2 + 1]);
                float m1 = __ldcg(&g_ms[(b * NS + 1) * 2]), s1 = __ldcg(&g_ms[(b * NS + 1) * 2 + 1]);
                float m2 = __ldcg(&g_ms[(b * NS + 2) * 2]), s2 = __ldcg(&g_ms[(b * NS + 2) * 2 + 1]);
                float m3 = __ldcg(&g_ms[(b * NS + 3) * 2]), s3 = __ldcg(&g_ms[(b * NS + 3) * 2 + 1]);
                float M = fmaxf(fmaxf(m0, m1), fmaxf(m2, m3));
                float e0 = __expf(m0 - M), e1 = __expf(m1 - M);
                float e2 = __expf(m2 - M), e3 = __expf(m3 - M);
                float rinv = __fdividef(1.0f, e0 * s0 + e1 * s1 + e2 * s2 + e3 * s3);
                #pragma unroll
                for (int i = 0; i < 8; i++) {
                    int j = ln + i * 32;
                    float cx = (e0 * __ldcg(&g_pctx[(b * NS + 0) * EHD + j])
                              + e1 * __ldcg(&g_pctx[(b * NS + 1) * EHD + j])
                              + e2 * __ldcg(&g_pctx[(b * NS + 2) * EHD + j])
                              + e3 * __ldcg(&g_pctx[(b * NS + 3) * EHD + j])) * rinv;
                    sm.c.ctx_s[bb][j] = cx;
                    if ((ch & 31) == 0) g_ctx[b * EHD + j] = cx;
                }
            }
            __syncthreads();

            {   // y_tilde
                const int bb = tid >> 5, ln = tid & 31;
                const int b = b0 + bb;
                #pragma unroll
                for (int y = 0; y < YD; y++) {
                    const float* wr = Wfc + y * 264;
                    float tt = 0.0f;
                    #pragma unroll
                    for (int k = ln; k < 256; k += 32) tt += wr[k] * sm.c.ctx_s[bb][k];
                    tt = warp_sum(tt);
                    if (ln == 0) {
                        const float* yp = g_yp[cur] + b * YD;
                        #pragma unroll
                        for (int k = 0; k < 8; k++) tt += wr[256 + k] * __ldcg(yp + k);
                        sm.c.yt_s[bb][y] = tt + bfc[y];
                    }
                }
            }
            __syncthreads();

            {   // gates
                const int jl = tid & 7;
                const int bl = (tid >> 3) & 7;
                const int gate = tid >> 6;
                const int b = b0 + bl;
                const int row = gate * 8 + jl;
                const float4* h4 = (const float4*)(g_h[cur] + b * DHD);
                float s = sm.c.bias_s[row];
                #pragma unroll 8
                for (int k4 = 0; k4 < 64; k4++) {
                    float4 hv = __ldcg(h4 + k4);
                    int k = k4 << 2;
                    s += sm.c.Ws[row][k] * hv.x + sm.c.Ws[row][k + 1] * hv.y
                       + sm.c.Ws[row][k + 2] * hv.z + sm.c.Ws[row][k + 3] * hv.w;
                }
                #pragma unroll
                for (int k = 0; k < 8; k++) s += sm.c.Wi_s[row][k] * sm.c.yt_s[bl][k];
                sm.c.gv[gate][(bl << 3) | jl] = s;
            }
            __syncthreads();

            if (tid < 64) {
                int jj = tid & 7, bb = tid >> 3;
                int gb = b0 + bb, gj = j0 + jj;
                float ig = sm.c.gv[0][tid], fg = sm.c.gv[1][tid];
                float gg = sm.c.gv[2][tid], og = sm.c.gv[3][tid];
                float cold = __ldcg(&g_c[cur][gb * DHD + gj]);
                float cn = fast_sig(fg) * cold + fast_sig(ig) * fast_tanh(gg);
                float hn = fast_sig(og) * fast_tanh(cn);
                g_c[nxt][gb * DHD + gj] = cn;
                g_h[nxt][gb * DHD + gj] = hn;
            }
            __syncthreads();
        }
        gsync((unsigned)NB, my_gen);
    }
}

// ---------------- launch ----------------
extern "C" void kernel_launch(void* const* d_in, const int* in_sizes, int n_in,
                              void* d_out, int out_size) {
    const float* x    = (const float*)d_in[0];
    const float* yh   = (const float*)d_in[1];
    const float* W1   = (const float*)d_in[2];
    const float* b1   = (const float*)d_in[3];
    const float* w2   = (const float*)d_in[4];
    const float* Wih  = (const float*)d_in[6];
    const float* Whh  = (const float*)d_in[7];
    const float* bih  = (const float*)d_in[8];
    const float* bhh  = (const float*)d_in[9];
    const float* Wfc  = (const float*)d_in[10];
    const float* bfc  = (const float*)d_in[11];
    const float* Wfin = (const float*)d_in[12];
    const float* bfin = (const float*)d_in[13];
    float* out = (float*)d_out;

    const int T = out_size / (BDIM * YD);

    int dev = 0;
    cudaGetDevice(&dev);
    int sms = 148;
    cudaDeviceGetAttribute(&sms, cudaDevAttrMultiProcessorCount, dev);
    int occ = 1;
    cudaOccupancyMaxActiveBlocksPerMultiprocessor(&occ, k_persist, 256, 0);
    if (occ < 1) occ = 1;
    long nb = (long)sms * (long)occ;
    if (nb > 512) nb = 512;

    k_init<<<BDIM, 256>>>(yh);
    k_convx<<<2048, 256>>>(x);
    k_convw<<<64, 256>>>(W1);
    k_projmma<<<dim3(2, 512), 256>>>();
    k_persist<<<(int)nb, 256>>>(W1, b1, w2, Whh, Wih, bih, bhh,
                                Wfc, bfc, Wfin, bfin, out, T, (int)nb);
}

// round 13
// speedup vs baseline: 1.5421x; 1.5421x over previous
#include <cuda_runtime.h>
#include <cuda_fp16.h>
#include <cstddef>
#include <cstdint>

#define BDIM 128
#define LDIM 512
#define EHD  256
#define DHD  256
#define YD   8

// ---------------- device scratch (static, allocation-free) ----------------
__device__ __half g_projh[(size_t)BDIM * LDIM * EHD]; // 32MB fp16 proj
__device__ __half g_xh[(size_t)BDIM * LDIM * EHD];    // 32MB fp16 x
__device__ __half g_wh[EHD * EHD];                    // W1x fp16 [n][k] (GEMM B)
__device__ __half g_whcT[512 * EHD];                  // W1[h,c] fp16 [k][j] transposed
__device__ float g_h[2][BDIM * DHD];
__device__ float g_c[2][BDIM * DHD];
__device__ float g_ctx[BDIM * EHD];
__device__ float g_yt[BDIM * YD];

// ---------------- math helpers ----------------
__device__ __forceinline__ float tanh_hw(float x) {
    float y; asm("tanh.approx.f32 %0, %1;" : "=f"(y) : "f"(x)); return y;
}
__device__ __forceinline__ float fast_tanh(float x) { // accurate, for LSTM
    float e = __expf(2.0f * x);
    return 1.0f - __fdividef(2.0f, e + 1.0f);
}
__device__ __forceinline__ float fast_sig(float x) {
    return __fdividef(1.0f, 1.0f + __expf(-x));
}
__device__ __forceinline__ float warp_sum(float v) {
    #pragma unroll
    for (int o = 16; o > 0; o >>= 1) v += __shfl_xor_sync(0xffffffffu, v, o);
    return v;
}
__device__ __forceinline__ float warp_max(float v) {
    #pragma unroll
    for (int o = 16; o > 0; o >>= 1) v = fmaxf(v, __shfl_xor_sync(0xffffffffu, v, o));
    return v;
}
__device__ __forceinline__ void mma_f16(float c[4], const uint32_t a[4],
                                        const uint32_t b[2]) {
    asm volatile(
        "mma.sync.aligned.m16n8k16.row.col.f32.f16.f16.f32 "
        "{%0,%1,%2,%3}, {%4,%5,%6,%7}, {%8,%9}, {%0,%1,%2,%3};\n"
        : "+f"(c[0]), "+f"(c[1]), "+f"(c[2]), "+f"(c[3])
        : "r"(a[0]), "r"(a[1]), "r"(a[2]), "r"(a[3]), "r"(b[0]), "r"(b[1]));
}

// ---------------- init + converts ----------------
__global__ void k_init() {
    int i = blockIdx.x * blockDim.x + threadIdx.x;
    if (i < BDIM * DHD) { g_h[0][i] = 0.0f; g_c[0][i] = 0.0f; }
}

__global__ __launch_bounds__(256) void k_convx(const float* __restrict__ x) {
    const int n4 = (BDIM * LDIM * EHD) / 4;
    for (int i = blockIdx.x * blockDim.x + threadIdx.x; i < n4;
         i += gridDim.x * blockDim.x) {
        float4 v = *(const float4*)(x + (size_t)i * 4);
        __half2 p0 = __floats2half2_rn(v.x, v.y);
        __half2 p1 = __floats2half2_rn(v.z, v.w);
        uint2 o; o.x = *(uint32_t*)&p0; o.y = *(uint32_t*)&p1;
        *(uint2*)(g_xh + (size_t)i * 4) = o;
    }
}

__global__ __launch_bounds__(256) void k_convw(const float* __restrict__ W1) {
    // GEMM B: W1x[n][k] = W1[n*768 + 512 + k], 256x256 -> fp16 (row-major k)
    int i = blockIdx.x * blockDim.x + threadIdx.x;   // 64x256 = 16384 float4
    int row = i >> 6;
    int c4 = (i & 63) * 4;
    float4 v = *(const float4*)(W1 + (size_t)row * 768 + 512 + c4);
    __half2 p0 = __floats2half2_rn(v.x, v.y);
    __half2 p1 = __floats2half2_rn(v.z, v.w);
    uint2 o; o.x = *(uint32_t*)&p0; o.y = *(uint32_t*)&p1;
    *(uint2*)(g_wh + (size_t)row * 256 + c4) = o;
}

__global__ __launch_bounds__(256) void k_convwT(const float* __restrict__ W1) {
    // g_whcT[k][j] = W1[j*768 + k], k in [0,512): h (k<256) and c (k>=256) weights.
    int k = blockIdx.x;          // 512 blocks
    int j = threadIdx.x;         // 256 threads
    g_whcT[k * EHD + j] = __float2half_rn(W1[(size_t)j * 768 + k]);
}

// ---------------- tensor-core proj GEMM (measured-good, unchanged) -----------
__global__ __launch_bounds__(256) void k_projmma() {
    __shared__ __half As[128][72];
    __shared__ __half Bs[128][72];
    const int bm = blockIdx.y * 128;
    const int bn = blockIdx.x * 128;
    const int tid = threadIdx.x;
    const int wid = tid >> 5, ln = tid & 31;
    const int wm = wid & 3, wn = wid >> 2;
    const int g = ln >> 2, tg2 = (ln & 3) * 2;

    float acc[2][8][4];
    #pragma unroll
    for (int mi = 0; mi < 2; mi++)
        #pragma unroll
        for (int ni = 0; ni < 8; ni++)
            #pragma unroll
            for (int q = 0; q < 4; q++) acc[mi][ni][q] = 0.0f;

    for (int kc = 0; kc < 4; kc++) {
        const int kb = kc * 64;
        #pragma unroll
        for (int it = 0; it < 4; it++) {
            int idx = it * 256 + tid;
            int row = idx >> 3;
            int col8 = (idx & 7) * 8;
            uint4 av = *(const uint4*)(g_xh + (size_t)(bm + row) * 256 + kb + col8);
            uint4 bv = *(const uint4*)(g_wh + (size_t)(bn + row) * 256 + kb + col8);
            *(uint4*)&As[row][col8] = av;
            *(uint4*)&Bs[row][col8] = bv;
        }
        __syncthreads();

        #pragma unroll
        for (int ks = 0; ks < 64; ks += 16) {
            uint32_t a[2][4], bf[8][2];
            #pragma unroll
            for (int mi = 0; mi < 2; mi++) {
                int mb = wm * 32 + mi * 16;
                a[mi][0] = *(const uint32_t*)&As[mb + g][ks + tg2];
                a[mi][1] = *(const uint32_t*)&As[mb + g + 8][ks + tg2];
                a[mi][2] = *(const uint32_t*)&As[mb + g][ks + tg2 + 8];
                a[mi][3] = *(const uint32_t*)&As[mb + g + 8][ks + tg2 + 8];
            }
            #pragma unroll
            for (int ni = 0; ni < 8; ni++) {
                int nb = wn * 64 + ni * 8;
                bf[ni][0] = *(const uint32_t*)&Bs[nb + g][ks + tg2];
                bf[ni][1] = *(const uint32_t*)&Bs[nb + g][ks + tg2 + 8];
            }
            #pragma unroll
            for (int mi = 0; mi < 2; mi++)
                #pragma unroll
                for (int ni = 0; ni < 8; ni++)
                    mma_f16(acc[mi][ni], a[mi], bf[ni]);
        }
        __syncthreads();
    }

    #pragma unroll
    for (int mi = 0; mi < 2; mi++) {
        int r0 = bm + wm * 32 + mi * 16 + g;
        #pragma unroll
        for (int ni = 0; ni < 8; ni++) {
            int col = bn + wn * 64 + ni * 8 + tg2;
            __half2 p0 = __floats2half2_rn(acc[mi][ni][0], acc[mi][ni][1]);
            __half2 p1 = __floats2half2_rn(acc[mi][ni][2], acc[mi][ni][3]);
            *(uint32_t*)&g_projh[(size_t)r0 * 256 + col] = *(uint32_t*)&p0;
            *(uint32_t*)&g_projh[(size_t)(r0 + 8) * 256 + col] = *(uint32_t*)&p1;
        }
    }
}

// ---------------- step kernel 1: ypred(t-1) + u + scores + softmax + ctx + yt
// grid = BDIM blocks (one per batch), 512 threads (16 warps).
__global__ __launch_bounds__(512) void k_step1(
    const float* __restrict__ b1,   const float* __restrict__ w2,
    const float* __restrict__ Wfc,  const float* __restrict__ bfc,
    const float* __restrict__ Wfin, const float* __restrict__ bfin,
    const float* __restrict__ yh,   float* __restrict__ out,
    int T, int t, int cur)
{
    __shared__ float h_s[DHD], c_s[DHD], u_s[EHD], w2_s[EHD];
    __shared__ float sc[LDIM];
    __shared__ float red[16];
    __shared__ float part4[4][EHD];
    __shared__ float yp_s[YD];
    const int b = blockIdx.x;
    const int tid = threadIdx.x;
    const int w = tid >> 5, ln = tid & 31;

    if (tid < 256) {
        h_s[tid] = g_h[cur][b * DHD + tid];
    } else {
        int k = tid - 256;
        c_s[k] = g_c[cur][b * DHD + k];
        w2_s[k] = w2[k];
    }
    __syncthreads();

    // ---- y_pred(t-1) (uses h(t)=g_h[cur], ctx(t-1)=g_ctx) ----
    if (t > 0) {
        if (w < 8) {
            const float* wr = Wfin + w * 512;
            const float* cx = g_ctx + b * EHD;
            float s = 0.0f;
            #pragma unroll
            for (int k = ln; k < 256; k += 32) s += wr[k] * h_s[k] + wr[256 + k] * cx[k];
            s = warp_sum(s);
            if (ln == 0) {
                float v = s + bfin[w];
                out[((size_t)b * T + (t - 1)) * YD + w] = v;
                yp_s[w] = v;
            }
        }
    } else {
        if (tid < YD) yp_s[tid] = yh[b * YD + tid];
    }
    if (t == T) return;   // epilogue call: ypred only

    // ---- u[j] = b1[j] + sum_k W1[j][k] h[k] + W1[j][256+k] c[k] ----
    // g_whcT is [k][j] fp16; quarters of k, j-pairs per thread.
    {
        int jp = (tid & 127) * 2, qf = tid >> 7;         // qf 0..3
        const float* vec = (qf < 2) ? h_s : c_s;
        int kb = (qf & 1) * 128;
        const __half* wt = g_whcT + (size_t)(qf * 128) * EHD + jp;
        float s0 = 0.0f, s1 = 0.0f;
        #pragma unroll 4
        for (int k = 0; k < 128; k++) {
            uint32_t pv = *(const uint32_t*)(wt + (size_t)k * EHD);
            float2 f = __half22float2(*(__half2*)&pv);
            float vv = vec[kb + k];
            s0 += f.x * vv; s1 += f.y * vv;
        }
        part4[qf][jp] = s0; part4[qf][jp + 1] = s1;
    }
    __syncthreads();
    if (tid < 256)
        u_s[tid] = part4[0][tid] + part4[1][tid] + part4[2][tid] + part4[3][tid] + b1[tid];
    __syncthreads();

    // ---- scores: warp w handles 32 l values ----
    {
        const int j0 = ln << 3;
        const float uw0 = u_s[j0],     uw1 = u_s[j0 + 1], uw2 = u_s[j0 + 2], uw3 = u_s[j0 + 3];
        const float uw4 = u_s[j0 + 4], uw5 = u_s[j0 + 5], uw6 = u_s[j0 + 6], uw7 = u_s[j0 + 7];
        const float w20 = w2_s[j0],     w21 = w2_s[j0 + 1], w22 = w2_s[j0 + 2], w23 = w2_s[j0 + 3];
        const float w24 = w2_s[j0 + 4], w25 = w2_s[j0 + 5], w26 = w2_s[j0 + 6], w27 = w2_s[j0 + 7];
        for (int li = 0; li < 32; li++) {
            int l = w * 32 + li;
            const uint4* p = (const uint4*)(g_projh + ((size_t)(b * LDIM + l)) * EHD);
            uint4 pv = p[ln];
            float2 f0 = __half22float2(*(__half2*)&pv.x);
            float2 f1 = __half22float2(*(__half2*)&pv.y);
            float2 f2 = __half22float2(*(__half2*)&pv.z);
            float2 f3 = __half22float2(*(__half2*)&pv.w);
            float s = w20 * tanh_hw(f0.x + uw0) + w21 * tanh_hw(f0.y + uw1)
                    + w22 * tanh_hw(f1.x + uw2) + w23 * tanh_hw(f1.y + uw3)
                    + w24 * tanh_hw(f2.x + uw4) + w25 * tanh_hw(f2.y + uw5)
                    + w26 * tanh_hw(f3.x + uw6) + w27 * tanh_hw(f3.y + uw7);
            s = warp_sum(s);
            if (ln == 0) sc[l] = s;
        }
    }
    __syncthreads();

    // ---- softmax over 512 (one value per thread) ----
    float rinv;
    {
        float v = sc[tid];
        float m = warp_max(v);
        if (ln == 0) red[w] = m;
        __syncthreads();
        float mx = red[0];
        #pragma unroll
        for (int i = 1; i < 16; i++) mx = fmaxf(mx, red[i]);
        __syncthreads();
        float e = __expf(v - mx);
        sc[tid] = e;
        float ss = warp_sum(e);
        if (ln == 0) red[w] = ss;
        __syncthreads();
        float tot = 0.0f;
        #pragma unroll
        for (int i = 0; i < 16; i++) tot += red[i];
        rinv = __fdividef(1.0f, tot);
    }

    // ---- context: thread = (j pair, l quarter) ----
    {
        int jp = (tid & 127) * 2, qf = tid >> 7;
        const __half* xb = g_xh + ((size_t)(b * LDIM) + qf * 128) * EHD + jp;
        float a0 = 0.0f, a1 = 0.0f;
        #pragma unroll 4
        for (int l = 0; l < 128; l++) {
            uint32_t pv = *(const uint32_t*)(xb + (size_t)l * EHD);
            float2 f = __half22float2(*(__half2*)&pv);
            float wv = sc[qf * 128 + l];
            a0 += wv * f.x; a1 += wv * f.y;
        }
        part4[qf][jp] = a0; part4[qf][jp + 1] = a1;
    }
    __syncthreads();
    if (tid < 256) {
        float cx = (part4[0][tid] + part4[1][tid] + part4[2][tid] + part4[3][tid]) * rinv;
        part4[0][tid] = cx;
        g_ctx[b * EHD + tid] = cx;
    }
    __syncthreads();

    // ---- y_tilde ----
    if (w < 8) {
        const float* wr = Wfc + w * 264;
        float s = 0.0f;
        #pragma unroll
        for (int k = ln; k < 256; k += 32) s += wr[k] * part4[0][k];
        s = warp_sum(s);
        if (ln == 0) {
            #pragma unroll
            for (int k = 0; k < 8; k++) s += wr[256 + k] * yp_s[k];
            g_yt[b * YD + w] = s + bfc[w];
        }
    }
}

// ---------------- step kernel 2: gates + LSTM cell (R5-validated form) -------
__global__ __launch_bounds__(256) void k_lstm(const float* __restrict__ Whh,
                                              const float* __restrict__ Wih,
                                              const float* __restrict__ bih,
                                              const float* __restrict__ bhh,
                                              int cur, int nxt) {
    __shared__ float Ws[32][257];
    __shared__ float Wi_s[32][9];
    __shared__ float bias_s[32];
    __shared__ float gv[4][64];
    const int j0 = blockIdx.x * 8;
    const int b0 = blockIdx.y * 8;
    const int tid = threadIdx.x;

    for (int idx = tid; idx < 32 * 64; idx += 256) {
        int row = idx >> 6;
        int col = (idx & 63) << 2;
        int g = (row >> 3) * 256 + j0 + (row & 7);
        float4 v = *(const float4*)(Whh + (size_t)g * 256 + col);
        Ws[row][col + 0] = v.x; Ws[row][col + 1] = v.y;
        Ws[row][col + 2] = v.z; Ws[row][col + 3] = v.w;
    }
    {
        int row = tid >> 3, k = tid & 7;
        int g = (row >> 3) * 256 + j0 + (row & 7);
        Wi_s[row][k] = Wih[(size_t)g * 8 + k];
        if (tid < 32) {
            int gg = (tid >> 3) * 256 + j0 + (tid & 7);
            bias_s[tid] = bih[gg] + bhh[gg];
        }
    }
    __syncthreads();

    const int jl = tid & 7;
    const int bl = (tid >> 3) & 7;
    const int gate = tid >> 6;
    const int b = b0 + bl;
    const int row = gate * 8 + jl;

    const float4* h4 = (const float4*)(g_h[cur] + b * DHD);
    float s = bias_s[row];
    #pragma unroll 8
    for (int k4 = 0; k4 < 64; k4++) {
        float4 hv = h4[k4];
        int k = k4 << 2;
        s += Ws[row][k] * hv.x + Ws[row][k + 1] * hv.y + Ws[row][k + 2] * hv.z + Ws[row][k + 3] * hv.w;
    }
    const float* yt = g_yt + b * YD;
    #pragma unroll
    for (int k = 0; k < 8; k++) s += Wi_s[row][k] * yt[k];
    gv[gate][(bl << 3) | jl] = s;
    __syncthreads();

    if (tid < 64) {
        int jj = tid & 7, bb = tid >> 3;
        int gb = b0 + bb, gj = j0 + jj;
        float ig = gv[0][tid], fg = gv[1][tid], gg = gv[2][tid], og = gv[3][tid];
        float cold = g_c[cur][gb * DHD + gj];
        float cn = fast_sig(fg) * cold + fast_sig(ig) * fast_tanh(gg);
        float hn = fast_sig(og) * fast_tanh(cn);
        g_c[nxt][gb * DHD + gj] = cn;
        g_h[nxt][gb * DHD + gj] = hn;
    }
}

// ---------------- launch ----------------
extern "C" void kernel_launch(void* const* d_in, const int* in_sizes, int n_in,
                              void* d_out, int out_size) {
    const float* x    = (const float*)d_in[0];
    const float* yh   = (const float*)d_in[1];
    const float* W1   = (const float*)d_in[2];
    const float* b1   = (const float*)d_in[3];
    const float* w2   = (const float*)d_in[4];
    const float* Wih  = (const float*)d_in[6];
    const float* Whh  = (const float*)d_in[7];
    const float* bih  = (const float*)d_in[8];
    const float* bhh  = (const float*)d_in[9];
    const float* Wfc  = (const float*)d_in[10];
    const float* bfc  = (const float*)d_in[11];
    const float* Wfin = (const float*)d_in[12];
    const float* bfin = (const float*)d_in[13];
    float* out = (float*)d_out;

    const int T = out_size / (BDIM * YD);

    k_init<<<BDIM, 256>>>();
    k_convx<<<2048, 256>>>(x);
    k_convw<<<64, 256>>>(W1);
    k_convwT<<<512, 256>>>(W1);
    k_projmma<<<dim3(2, 512), 256>>>();

    for (int t = 0; t < T; t++) {
        int cur = t & 1, nxt = cur ^ 1;
        k_step1<<<BDIM, 512>>>(b1, w2, Wfc, bfc, Wfin, bfin, yh, out, T, t, cur);
        k_lstm<<<dim3(32, 16), 256>>>(Whh, Wih, bih, bhh, cur, nxt);
    }
    // epilogue: y_pred(T-1); h(T) is in g_h[T&1]
    k_step1<<<BDIM, 512>>>(b1, w2, Wfc, bfc, Wfin, bfin, yh, out, T, T, T & 1);
}

// round 14
// speedup vs baseline: 1.9038x; 1.2345x over previous
#include <cuda_runtime.h>
#include <cuda_fp16.h>
#include <cstddef>
#include <cstdint>

#define BDIM 128
#define LDIM 512
#define EHD  256
#define DHD  256
#define YD   8

// ---------------- device scratch (static, allocation-free) ----------------
__device__ __half g_projh[(size_t)BDIM * LDIM * EHD]; // 32MB fp16 proj
__device__ __half g_xh[(size_t)BDIM * LDIM * EHD];    // 32MB fp16 x
__device__ __half g_wh[EHD * EHD];                    // W1x fp16 [n][k] (GEMM B)
__device__ __half g_whcT[512 * EHD];                  // W1[h,c] fp16 [k][j]
__device__ uint32_t g_whhT2[128 * 1024];              // Whh half2 (2k,2k+1) at [k2][row]
__device__ float g_wihT[8 * 1024];                    // Wih [y][row]
__device__ float g_bias[1024];                        // bih + bhh

// ---------------- math helpers ----------------
__device__ __forceinline__ float tanh_hw(float x) {
    float y; asm("tanh.approx.f32 %0, %1;" : "=f"(y) : "f"(x)); return y;
}
__device__ __forceinline__ float fast_tanh(float x) { // accurate, for LSTM
    float e = __expf(2.0f * x);
    return 1.0f - __fdividef(2.0f, e + 1.0f);
}
__device__ __forceinline__ float fast_sig(float x) {
    return __fdividef(1.0f, 1.0f + __expf(-x));
}
__device__ __forceinline__ float warp_sum(float v) {
    #pragma unroll
    for (int o = 16; o > 0; o >>= 1) v += __shfl_xor_sync(0xffffffffu, v, o);
    return v;
}
__device__ __forceinline__ float warp_max(float v) {
    #pragma unroll
    for (int o = 16; o > 0; o >>= 1) v = fmaxf(v, __shfl_xor_sync(0xffffffffu, v, o));
    return v;
}
__device__ __forceinline__ void mma_f16(float c[4], const uint32_t a[4],
                                        const uint32_t b[2]) {
    asm volatile(
        "mma.sync.aligned.m16n8k16.row.col.f32.f16.f16.f32 "
        "{%0,%1,%2,%3}, {%4,%5,%6,%7}, {%8,%9}, {%0,%1,%2,%3};\n"
        : "+f"(c[0]), "+f"(c[1]), "+f"(c[2]), "+f"(c[3])
        : "r"(a[0]), "r"(a[1]), "r"(a[2]), "r"(a[3]), "r"(b[0]), "r"(b[1]));
}

// ---------------- converts ----------------
__global__ __launch_bounds__(256) void k_convx(const float* __restrict__ x) {
    const int n4 = (BDIM * LDIM * EHD) / 4;
    for (int i = blockIdx.x * blockDim.x + threadIdx.x; i < n4;
         i += gridDim.x * blockDim.x) {
        float4 v = *(const float4*)(x + (size_t)i * 4);
        __half2 p0 = __floats2half2_rn(v.x, v.y);
        __half2 p1 = __floats2half2_rn(v.z, v.w);
        uint2 o; o.x = *(uint32_t*)&p0; o.y = *(uint32_t*)&p1;
        *(uint2*)(g_xh + (size_t)i * 4) = o;
    }
}

__global__ __launch_bounds__(256) void k_convw(const float* __restrict__ W1) {
    int i = blockIdx.x * blockDim.x + threadIdx.x;   // 64x256 = 16384 float4
    int row = i >> 6;
    int c4 = (i & 63) * 4;
    float4 v = *(const float4*)(W1 + (size_t)row * 768 + 512 + c4);
    __half2 p0 = __floats2half2_rn(v.x, v.y);
    __half2 p1 = __floats2half2_rn(v.z, v.w);
    uint2 o; o.x = *(uint32_t*)&p0; o.y = *(uint32_t*)&p1;
    *(uint2*)(g_wh + (size_t)row * 256 + c4) = o;
}

__global__ __launch_bounds__(256) void k_convwT(const float* __restrict__ W1) {
    // g_whcT[k][j] = W1[j*768 + k], k in [0,512): h then c weights.
    int k = blockIdx.x;          // 512 blocks
    int j = threadIdx.x;         // 256 threads
    g_whcT[k * EHD + j] = __float2half_rn(W1[(size_t)j * 768 + k]);
}

__global__ __launch_bounds__(256) void k_convwhh(const float* __restrict__ Whh,
                                                 const float* __restrict__ Wih,
                                                 const float* __restrict__ bih,
                                                 const float* __restrict__ bhh) {
    int idx = blockIdx.x * blockDim.x + threadIdx.x;  // 512*256 = 131072
    int k2 = idx >> 10, r = idx & 1023;
    __half2 p = __floats2half2_rn(Whh[(size_t)r * 256 + 2 * k2],
                                  Whh[(size_t)r * 256 + 2 * k2 + 1]);
    g_whhT2[idx] = *(uint32_t*)&p;     // idx == k2*1024 + r
    if (idx < 8 * 1024) {
        int y = idx >> 10, rr = idx & 1023;
        g_wihT[idx] = Wih[(size_t)rr * 8 + y];
    }
    if (idx < 1024) g_bias[idx] = bih[idx] + bhh[idx];
}

// ---------------- tensor-core proj GEMM (measured-good, unchanged) -----------
__global__ __launch_bounds__(256) void k_projmma() {
    __shared__ __half As[128][72];
    __shared__ __half Bs[128][72];
    const int bm = blockIdx.y * 128;
    const int bn = blockIdx.x * 128;
    const int tid = threadIdx.x;
    const int wid = tid >> 5, ln = tid & 31;
    const int wm = wid & 3, wn = wid >> 2;
    const int g = ln >> 2, tg2 = (ln & 3) * 2;

    float acc[2][8][4];
    #pragma unroll
    for (int mi = 0; mi < 2; mi++)
        #pragma unroll
        for (int ni = 0; ni < 8; ni++)
            #pragma unroll
            for (int q = 0; q < 4; q++) acc[mi][ni][q] = 0.0f;

    for (int kc = 0; kc < 4; kc++) {
        const int kb = kc * 64;
        #pragma unroll
        for (int it = 0; it < 4; it++) {
            int idx = it * 256 + tid;
            int row = idx >> 3;
            int col8 = (idx & 7) * 8;
            uint4 av = *(const uint4*)(g_xh + (size_t)(bm + row) * 256 + kb + col8);
            uint4 bv = *(const uint4*)(g_wh + (size_t)(bn + row) * 256 + kb + col8);
            *(uint4*)&As[row][col8] = av;
            *(uint4*)&Bs[row][col8] = bv;
        }
        __syncthreads();

        #pragma unroll
        for (int ks = 0; ks < 64; ks += 16) {
            uint32_t a[2][4], bf[8][2];
            #pragma unroll
            for (int mi = 0; mi < 2; mi++) {
                int mb = wm * 32 + mi * 16;
                a[mi][0] = *(const uint32_t*)&As[mb + g][ks + tg2];
                a[mi][1] = *(const uint32_t*)&As[mb + g + 8][ks + tg2];
                a[mi][2] = *(const uint32_t*)&As[mb + g][ks + tg2 + 8];
                a[mi][3] = *(const uint32_t*)&As[mb + g + 8][ks + tg2 + 8];
            }
            #pragma unroll
            for (int ni = 0; ni < 8; ni++) {
                int nb = wn * 64 + ni * 8;
                bf[ni][0] = *(const uint32_t*)&Bs[nb + g][ks + tg2];
                bf[ni][1] = *(const uint32_t*)&Bs[nb + g][ks + tg2 + 8];
            }
            #pragma unroll
            for (int mi = 0; mi < 2; mi++)
                #pragma unroll
                for (int ni = 0; ni < 8; ni++)
                    mma_f16(acc[mi][ni], a[mi], bf[ni]);
        }
        __syncthreads();
    }

    #pragma unroll
    for (int mi = 0; mi < 2; mi++) {
        int r0 = bm + wm * 32 + mi * 16 + g;
        #pragma unroll
        for (int ni = 0; ni < 8; ni++) {
            int col = bn + wn * 64 + ni * 8 + tg2;
            __half2 p0 = __floats2half2_rn(acc[mi][ni][0], acc[mi][ni][1]);
            __half2 p1 = __floats2half2_rn(acc[mi][ni][2], acc[mi][ni][3]);
            *(uint32_t*)&g_projh[(size_t)r0 * 256 + col] = *(uint32_t*)&p0;
            *(uint32_t*)&g_projh[(size_t)(r0 + 8) * 256 + col] = *(uint32_t*)&p1;
        }
    }
}

// ---------------- persistent per-batch decode --------------------------------
// One block per batch element runs ALL T steps. No cross-block dependencies,
// no grid syncs, h/c/y_prev live in shared memory for the whole recurrence.
__global__ __launch_bounds__(512) void k_decode(
    const float* __restrict__ b1,   const float* __restrict__ w2,
    const float* __restrict__ Wfc,  const float* __restrict__ bfc,
    const float* __restrict__ Wfin, const float* __restrict__ bfin,
    const float* __restrict__ yh,   float* __restrict__ out, int T)
{
    __shared__ float h_s[DHD], c_s[DHD], u_s[EHD], w2_s[EHD];
    __shared__ float sc[LDIM];
    __shared__ float red[16];
    __shared__ float part4[4][EHD];
    __shared__ float ctx_s[EHD];
    __shared__ float yp_s[YD], yt_s[YD];
    __shared__ float fo_s[2][EHD];
    const int b = blockIdx.x;
    const int tid = threadIdx.x;
    const int w = tid >> 5, ln = tid & 31;

    if (tid < 256) { h_s[tid] = 0.0f; c_s[tid] = 0.0f; w2_s[tid] = w2[tid]; }
    if (tid < YD)  yp_s[tid] = yh[b * YD + tid];
    __syncthreads();

    for (int t = 0; t < T; t++) {
        // ---- u[j] = b1[j] + W1h[j,:].h + W1c[j,:].c (whcT is [k][j] fp16) ----
        {
            int jp = (tid & 127) * 2, qf = tid >> 7;   // qf: 0,1 -> h; 2,3 -> c
            const float* vec = (qf & 2) ? c_s : h_s;
            int kb = (qf & 1) * 128;
            const __half* wt = g_whcT + (size_t)(qf * 128) * EHD + jp;
            float s0 = 0.0f, s1 = 0.0f;
            #pragma unroll 4
            for (int k = 0; k < 128; k++) {
                uint32_t pv = *(const uint32_t*)(wt + (size_t)k * EHD);
                float2 f = __half22float2(*(__half2*)&pv);
                float vv = vec[kb + k];
                s0 += f.x * vv; s1 += f.y * vv;
            }
            part4[qf][jp] = s0; part4[qf][jp + 1] = s1;
        }
        __syncthreads();
        if (tid < 256)
            u_s[tid] = part4[0][tid] + part4[1][tid] + part4[2][tid] + part4[3][tid] + b1[tid];
        __syncthreads();

        // ---- scores: warp w handles 32 l values ----
        {
            const int j0 = ln << 3;
            const float uw0 = u_s[j0],     uw1 = u_s[j0 + 1], uw2 = u_s[j0 + 2], uw3 = u_s[j0 + 3];
            const float uw4 = u_s[j0 + 4], uw5 = u_s[j0 + 5], uw6 = u_s[j0 + 6], uw7 = u_s[j0 + 7];
            const float w20 = w2_s[j0],     w21 = w2_s[j0 + 1], w22 = w2_s[j0 + 2], w23 = w2_s[j0 + 3];
            const float w24 = w2_s[j0 + 4], w25 = w2_s[j0 + 5], w26 = w2_s[j0 + 6], w27 = w2_s[j0 + 7];
            for (int li = 0; li < 32; li++) {
                int l = w * 32 + li;
                const uint4* p = (const uint4*)(g_projh + ((size_t)(b * LDIM + l)) * EHD);
                uint4 pv = p[ln];
                float2 f0 = __half22float2(*(__half2*)&pv.x);
                float2 f1 = __half22float2(*(__half2*)&pv.y);
                float2 f2 = __half22float2(*(__half2*)&pv.z);
                float2 f3 = __half22float2(*(__half2*)&pv.w);
                float s = w20 * tanh_hw(f0.x + uw0) + w21 * tanh_hw(f0.y + uw1)
                        + w22 * tanh_hw(f1.x + uw2) + w23 * tanh_hw(f1.y + uw3)
                        + w24 * tanh_hw(f2.x + uw4) + w25 * tanh_hw(f2.y + uw5)
                        + w26 * tanh_hw(f3.x + uw6) + w27 * tanh_hw(f3.y + uw7);
                s = warp_sum(s);
                if (ln == 0) sc[l] = s;
            }
        }
        __syncthreads();

        // ---- softmax over 512 (one value per thread) ----
        float rinv;
        {
            float v = sc[tid];
            float m = warp_max(v);
            if (ln == 0) red[w] = m;
            __syncthreads();
            float mx = red[0];
            #pragma unroll
            for (int i = 1; i < 16; i++) mx = fmaxf(mx, red[i]);
            __syncthreads();
            float e = __expf(v - mx);
            sc[tid] = e;
            float ss = warp_sum(e);
            if (ln == 0) red[w] = ss;
            __syncthreads();
            float tot = 0.0f;
            #pragma unroll
            for (int i = 0; i < 16; i++) tot += red[i];
            rinv = __fdividef(1.0f, tot);
        }

        // ---- context: thread = (j pair, l quarter) ----
        {
            int jp = (tid & 127) * 2, qf = tid >> 7;
            const __half* xb = g_xh + ((size_t)(b * LDIM) + qf * 128) * EHD + jp;
            float a0 = 0.0f, a1 = 0.0f;
            #pragma unroll 4
            for (int l = 0; l < 128; l++) {
                uint32_t pv = *(const uint32_t*)(xb + (size_t)l * EHD);
                float2 f = __half22float2(*(__half2*)&pv);
                float wv = sc[qf * 128 + l];
                a0 += wv * f.x; a1 += wv * f.y;
            }
            part4[qf][jp] = a0; part4[qf][jp + 1] = a1;
        }
        __syncthreads();
        if (tid < 256)
            ctx_s[tid] = (part4[0][tid] + part4[1][tid] + part4[2][tid] + part4[3][tid]) * rinv;
        __syncthreads();

        // ---- y_tilde (warps 0-7) ----
        if (w < 8) {
            const float* wr = Wfc + w * 264;
            float s = 0.0f;
            #pragma unroll
            for (int k = ln; k < 256; k += 32) s += wr[k] * ctx_s[k];
            s = warp_sum(s);
            if (ln == 0) {
                #pragma unroll
                for (int k = 0; k < 8; k++) s += wr[256 + k] * yp_s[k];
                yt_s[w] = s + bfc[w];
            }
        }
        __syncthreads();

        // ---- gates: thread computes rows tid and tid+512 ----
        {
            float sA = g_bias[tid], sB = g_bias[tid + 512];
            #pragma unroll 4
            for (int k2 = 0; k2 < 128; k2++) {
                uint32_t av = g_whhT2[k2 * 1024 + tid];
                uint32_t bv = g_whhT2[k2 * 1024 + tid + 512];
                float2 fa = __half22float2(*(__half2*)&av);
                float2 fb = __half22float2(*(__half2*)&bv);
                float h0 = h_s[2 * k2], h1 = h_s[2 * k2 + 1];
                sA += fa.x * h0 + fa.y * h1;
                sB += fb.x * h0 + fb.y * h1;
            }
            #pragma unroll
            for (int y = 0; y < 8; y++) {
                float yv = yt_s[y];
                sA += g_wihT[y * 1024 + tid] * yv;
                sB += g_wihT[y * 1024 + tid + 512] * yv;
            }
            // tid<256: sA=i[j], sB=g[j]; tid>=256: sA=f[j], sB=o[j] (j=tid-256)
            if (tid >= 256) { fo_s[0][tid - 256] = sA; fo_s[1][tid - 256] = sB; }
            __syncthreads();
            if (tid < 256) {
                float fg = fo_s[0][tid], og = fo_s[1][tid];
                float cn = fast_sig(fg) * c_s[tid] + fast_sig(sA) * fast_tanh(sB);
                float hn = fast_sig(og) * fast_tanh(cn);
                c_s[tid] = cn;
                h_s[tid] = hn;
            }
        }
        __syncthreads();

        // ---- y_pred(t) = Wfin.[h_new, ctx] + bfin (warps 0-7) ----
        if (w < 8) {
            const float* wr = Wfin + w * 512;
            float s = 0.0f;
            #pragma unroll
            for (int k = ln; k < 256; k += 32) s += wr[k] * h_s[k] + wr[256 + k] * ctx_s[k];
            s = warp_sum(s);
            if (ln == 0) {
                float v = s + bfin[w];
                out[((size_t)b * T + t) * YD + w] = v;
                yp_s[w] = v;
            }
        }
        __syncthreads();
    }
}

// ---------------- launch ----------------
extern "C" void kernel_launch(void* const* d_in, const int* in_sizes, int n_in,
                              void* d_out, int out_size) {
    const float* x    = (const float*)d_in[0];
    const float* yh   = (const float*)d_in[1];
    const float* W1   = (const float*)d_in[2];
    const float* b1   = (const float*)d_in[3];
    const float* w2   = (const float*)d_in[4];
    const float* Wih  = (const float*)d_in[6];
    const float* Whh  = (const float*)d_in[7];
    const float* bih  = (const float*)d_in[8];
    const float* bhh  = (const float*)d_in[9];
    const float* Wfc  = (const float*)d_in[10];
    const float* bfc  = (const float*)d_in[11];
    const float* Wfin = (const float*)d_in[12];
    const float* bfin = (const float*)d_in[13];
    float* out = (float*)d_out;

    const int T = out_size / (BDIM * YD);

    k_convx<<<2048, 256>>>(x);
    k_convw<<<64, 256>>>(W1);
    k_convwT<<<512, 256>>>(W1);
    k_convwhh<<<512, 256>>>(Whh, Wih, bih, bhh);
    k_projmma<<<dim3(2, 512), 256>>>();
    k_decode<<<BDIM, 512>>>(b1, w2, Wfc, bfc, Wfin, bfin, yh, out, T);
}